// round 8
// baseline (speedup 1.0000x reference)
#include <cuda_runtime.h>
#include <cuda_bf16.h>
#include <cstdint>
#include <cstddef>

#define SEQ   512
#define BATCH 64
#define HS    1024
#define NG    4096
#define MROWS (SEQ*BATCH)     // 32768
#define NB_PERS 128
#define UNITS 8
#define GP 36                 // padded gate-smem row stride (floats)
#define HB (BATCH*2*HS)       // one h buffer (hi|lo), elements
#define SMEM_LAYER (1024 + 131072 + 32768 + 9216 + 256)
// phase1: V 128K | A 32K | U 16K | gates 9216 | pre0 ping-pong 18432 | align 1024
#define SMEM_P1 (1024 + 131072 + 32768 + 16384 + 9216 + 18432)

typedef unsigned long long u64;
typedef __nv_bfloat16 bf16;

// ---------------- static device scratch ----------------
__device__ float g_pre[(size_t)MROWS * NG];          // layer-1 gate pre-activations
__device__ bf16  g_xs[(size_t)MROWS * 2 * HS];       // input splits (hi|lo)
__device__ bf16  g_hs[2 * HB];                       // double-buffered h splits
__device__ bf16  g_Us0[(size_t)NG * 2 * HS];         // permuted weight splits
__device__ bf16  g_Vs0[(size_t)NG * 2 * HS];
__device__ bf16  g_Us1[(size_t)NG * 2 * HS];
__device__ bf16  g_Vs1[(size_t)NG * 2 * HS];

// ---------------- grid barrier (release/acquire, monotonic gen) ----------------
__device__ unsigned g_cnt = 0;
__device__ unsigned g_gen = 0;

__device__ __forceinline__ void grid_barrier(unsigned& mygen) {
    __syncthreads();
    if (threadIdx.x == 0) {
        unsigned old;
        asm volatile("atom.add.acq_rel.gpu.u32 %0, [%1], 1;"
                     : "=r"(old) : "l"(&g_cnt) : "memory");
        if (old == (unsigned)(NB_PERS - 1)) {
            asm volatile("st.relaxed.gpu.u32 [%0], 0;" :: "l"(&g_cnt) : "memory");
            asm volatile("red.release.gpu.add.u32 [%0], 1;" :: "l"(&g_gen) : "memory");
        } else {
            unsigned cur;
            do {
                __nanosleep(20);
                asm volatile("ld.acquire.gpu.u32 %0, [%1];"
                             : "=r"(cur) : "l"(&g_gen) : "memory");
            } while (cur == mygen);
        }
    }
    mygen += 1;
    __syncthreads();
}

// ---------------- mma.sync building blocks (validated R4-R7) ----------------
__device__ __forceinline__ uint32_t smem_u32(const void* p) {
    uint32_t a;
    asm("{ .reg .u64 t; cvta.to.shared.u64 t, %1; cvt.u32.u64 %0, t; }" : "=r"(a) : "l"(p));
    return a;
}
__device__ __forceinline__ void ldsm4(uint32_t* f, uint32_t addr) {
    asm volatile("ldmatrix.sync.aligned.m8n8.x4.shared.b16 {%0,%1,%2,%3}, [%4];"
        : "=r"(f[0]), "=r"(f[1]), "=r"(f[2]), "=r"(f[3]) : "r"(addr));
}
__device__ __forceinline__ void mma16816(float* d, const uint32_t* a, uint32_t b0, uint32_t b1) {
    asm volatile("mma.sync.aligned.m16n8k16.row.col.f32.bf16.bf16.f32 "
        "{%0,%1,%2,%3}, {%4,%5,%6,%7}, {%8,%9}, {%0,%1,%2,%3};"
        : "+f"(d[0]), "+f"(d[1]), "+f"(d[2]), "+f"(d[3])
        : "r"(a[0]), "r"(a[1]), "r"(a[2]), "r"(a[3]), "r"(b0), "r"(b1));
}
__device__ __forceinline__ uint32_t swz(uint32_t r, uint32_t c16) {
    return r * 128u + ((c16 ^ (r & 7u)) << 4);
}
__device__ __forceinline__ uint32_t a_addr(uint32_t base, int lane, int m0, int k0) {
    int sel = lane >> 3;
    uint32_t row = (uint32_t)(m0 + (lane & 7) + ((sel & 1) << 3));
    uint32_t c16 = (uint32_t)((k0 >> 3) + (sel >> 1));
    return base + swz(row, c16);
}
__device__ __forceinline__ uint32_t b_addr(uint32_t base, int lane, int n0, int k0) {
    int sel = lane >> 3;
    uint32_t row = (uint32_t)(n0 + (lane & 7) + ((sel >> 1) << 3));
    uint32_t c16 = (uint32_t)((k0 >> 3) + (sel & 1));
    return base + swz(row, c16);
}
__device__ __forceinline__ void cp16(uint32_t dst, const void* src) {
    asm volatile("cp.async.cg.shared.global [%0], [%1], 16;" :: "r"(dst), "l"(src));
}

// sync-path tile load (used for resident V slices)
__device__ __forceinline__ void load_tile(uint32_t sdst, const bf16* __restrict__ src,
                                          int rows, int ld) {
    const int chunks = rows * 8;
    for (int i = threadIdx.x; i < chunks; i += 256) {
        int r = i >> 3, c = i & 7;
        const uint4* p = reinterpret_cast<const uint4*>(src + (size_t)r * ld + c * 8);
        uint4 v = __ldg(p);
        asm volatile("st.shared.v4.b32 [%0], {%1,%2,%3,%4};"
                     :: "r"(sdst + swz((uint32_t)r, (uint32_t)c)),
                        "r"(v.x), "r"(v.y), "r"(v.z), "r"(v.w));
    }
}
// async stage: A pair (64 rows x 64 cols, hi tile + lo tile of 8KB each).
// src = row base (stride 2048); hi at +0, lo at +1024.
__device__ __forceinline__ void stage_A(uint32_t sdst, const bf16* __restrict__ src) {
    const int tid = threadIdx.x;
#pragma unroll
    for (int s = 0; s < 2; s++) {
#pragma unroll
        for (int q = 0; q < 2; q++) {
            int i = tid + q * 256;
            int r = i >> 3, c = i & 7;
            cp16(sdst + (uint32_t)s * 8192u + swz((uint32_t)r, (uint32_t)c),
                 src + s * 1024 + (size_t)r * 2048 + c * 8);
        }
    }
}
// async stage: U pair (32 rows x 64 cols, hi 4KB + lo 4KB)
__device__ __forceinline__ void stage_U(uint32_t sdst, const bf16* __restrict__ src) {
    const int tid = threadIdx.x;
    int r = tid >> 3, c = tid & 7;     // 256 threads = exactly 32x8 chunks
#pragma unroll
    for (int s = 0; s < 2; s++)
        cp16(sdst + (uint32_t)s * 4096u + swz((uint32_t)r, (uint32_t)c),
             src + s * 1024 + (size_t)r * 2048 + c * 8);
}

// ---------------- activations ----------------
__device__ __forceinline__ float sigmoid_acc(float x) {
    return 1.0f / (1.0f + __expf(-x));
}
__device__ __forceinline__ float tanh_acc(float x) {
    float e = __expf(-2.0f * fabsf(x));
    float t = (1.0f - e) / (1.0f + e);
    return copysignf(t, x);
}
__device__ __forceinline__ void split2(float v, bf16& hi, bf16& lo) {
    hi = __float2bfloat16(v);
    lo = __float2bfloat16(v - __bfloat162float(hi));
}

// =================================================================================
// split kernels. Weight rows gate-permuted: orig row r = g*1024+u -> 4u+g.
// =================================================================================
__global__ __launch_bounds__(256) void k_split_x(const float* __restrict__ x) {
    size_t i = (size_t)blockIdx.x * 256 + threadIdx.x;
    size_t m = i >> 10, k = i & 1023;
    bf16 hi, lo; split2(x[i], hi, lo);
    g_xs[m * 2048 + k]        = hi;
    g_xs[m * 2048 + 1024 + k] = lo;
}
__global__ __launch_bounds__(256) void k_split_w4(
    const float* __restrict__ W0, const float* __restrict__ W1,
    const float* __restrict__ W2, const float* __restrict__ W3,
    bf16* __restrict__ d0, bf16* __restrict__ d1,
    bf16* __restrict__ d2, bf16* __restrict__ d3)
{
    const float* W; bf16* dst;
    switch (blockIdx.y) {
        case 0:  W = W0; dst = d0; break;
        case 1:  W = W1; dst = d1; break;
        case 2:  W = W2; dst = d2; break;
        default: W = W3; dst = d3; break;
    }
    size_t i = (size_t)blockIdx.x * 256 + threadIdx.x;
    size_t n = i >> 10, k = i & 1023;
    size_t gidx = n >> 10, u = n & 1023;
    size_t np = u * 4 + gidx;
    bf16 hi, lo; split2(W[i], hi, lo);
    dst[np * 2048 + k]        = hi;
    dst[np * 2048 + 1024 + k] = lo;
}

// =================================================================================
// PHASE 1 (persistent, 128 CTAs): per step t:
//   fused loop (A = h0[t-1] splits): recurrent0 (B=V0 smem-resident) AND
//                                    inproj1[t-1] (B=U1 streamed) -> g_pre
//   ip0 loop   (A = x[t+1] splits):  inproj0[t+1] (B=U0 streamed) -> sP0 ping-pong
//   pointwise (recGates + sP0[t&1] + bias), publish h0[t], grid barrier.
// Extra iteration t==SEQ computes inproj1[SEQ-1] only.
// =================================================================================
__global__ __launch_bounds__(256) void k_phase1(
    const bf16* __restrict__ Vs, const bf16* __restrict__ Us0,
    const bf16* __restrict__ Us1, const bf16* __restrict__ xs,
    const float* __restrict__ b1, const float* __restrict__ b2,
    float* __restrict__ pre_out, float* __restrict__ dh, float* __restrict__ dc)
{
    extern __shared__ char dsm[];
    const uint32_t sbase = (smem_u32(dsm) + 1023u) & ~1023u;
    const uint32_t sV  = sbase;                    // 32 tiles x 4096
    const uint32_t sA  = sbase + 131072u;          // 2 buf x 16384
    const uint32_t sU  = sbase + 163840u;          // 2 buf x 8192
    const uint32_t sG  = sbase + 180224u;          // 64*GP fp32
    const uint32_t sP0 = sbase + 189440u;          // 2 x 9216
    const int tid = threadIdx.x, wid = tid >> 5, lane = tid & 31;
    const int bx = blockIdx.x;
    const int mi = wid & 3, ni = wid >> 2;
    const int b  = tid >> 2;
    const int ul = (tid & 3) * 2;
    const int u0g = bx * UNITS + ul;
    const int col0 = bx * 32 + 4 * ul;
    const int epi_r = lane >> 2, epi_c = (lane & 3) * 2;

    const bf16* Urow0 = Us0 + (size_t)(bx * 32) * 2048;
    const bf16* Urow1 = Us1 + (size_t)(bx * 32) * 2048;

    // V0 slice resident
    for (int s = 0; s < 2; s++)
        for (int kb = 0; kb < 16; kb++)
            load_tile(sV + (uint32_t)(s * 16 + kb) * 4096u,
                      Vs + (size_t)(bx * 32) * 2048 + s * 1024 + kb * 64,
                      32, 2048);

    float bias[8];
#pragma unroll
    for (int j = 0; j < 8; j++) {
        int n = col0 + j;
        int orig = ((n & 3) << 10) + (n >> 2);
        bias[j] = __ldg(b1 + orig) + __ldg(b2 + orig);
    }

    unsigned mygen;
    asm volatile("ld.relaxed.gpu.u32 %0, [%1];" : "=r"(mygen) : "l"(&g_gen));

    float2 c2 = make_float2(0.f, 0.f), h2 = make_float2(0.f, 0.f);
    __stcg(reinterpret_cast<unsigned*>(g_hs + (size_t)HB + b * 2048 + u0g), 0u);
    __stcg(reinterpret_cast<unsigned*>(g_hs + (size_t)HB + b * 2048 + 1024 + u0g), 0u);
    __syncthreads();   // V/smem writes done before first ldsm use

    // ---- prologue: inproj0[0] -> sP0[0] ----
    {
        const bf16* xsrc = xs;   // rows 0..63
        stage_A(sA, xsrc); stage_U(sU, Urow0);
        asm volatile("cp.async.commit_group;");
        float a0[2][4];
#pragma unroll
        for (int f = 0; f < 2; f++)
#pragma unroll
            for (int j = 0; j < 4; j++) a0[f][j] = 0.f;
#pragma unroll 1
        for (int kb = 0; kb < 16; kb++) {
            asm volatile("cp.async.wait_group 0;");
            __syncthreads();
            if (kb < 15) {
                stage_A(sA + (uint32_t)((kb + 1) & 1) * 16384u, xsrc + (kb + 1) * 64);
                stage_U(sU + (uint32_t)((kb + 1) & 1) * 8192u,  Urow0 + (kb + 1) * 64);
                asm volatile("cp.async.commit_group;");
            }
            const uint32_t ahB = sA + (uint32_t)(kb & 1) * 16384u, alB = ahB + 8192u;
            const uint32_t uhB = sU + (uint32_t)(kb & 1) * 8192u,  ulB = uhB + 4096u;
#pragma unroll
            for (int kst = 0; kst < 4; kst++) {
                const int k0 = kst * 16;
                uint32_t ah[4], al[4], bh[4], bl[4];
                ldsm4(ah, a_addr(ahB, lane, mi * 16, k0));
                ldsm4(bh, b_addr(uhB, lane, ni * 16, k0));
                ldsm4(al, a_addr(alB, lane, mi * 16, k0));
                ldsm4(bl, b_addr(ulB, lane, ni * 16, k0));
                mma16816(a0[0], ah, bh[0], bh[1]);
                mma16816(a0[1], ah, bh[2], bh[3]);
                mma16816(a0[0], al, bh[0], bh[1]);
                mma16816(a0[1], al, bh[2], bh[3]);
                mma16816(a0[0], ah, bl[0], bl[1]);
                mma16816(a0[1], ah, bl[2], bl[3]);
            }
        }
        const int row = mi * 16 + epi_r;
#pragma unroll
        for (int f = 0; f < 2; f++) {
            const int col = ni * 16 + f * 8 + epi_c;
            asm volatile("st.shared.v2.f32 [%0], {%1,%2};"
                :: "r"(sP0 + (uint32_t)(row * GP + col) * 4u), "f"(a0[f][0]), "f"(a0[f][1]));
            asm volatile("st.shared.v2.f32 [%0], {%1,%2};"
                :: "r"(sP0 + (uint32_t)((row + 8) * GP + col) * 4u), "f"(a0[f][2]), "f"(a0[f][3]));
        }
    }
    grid_barrier(mygen);

    // ---- main loop; t == SEQ is the inproj1[SEQ-1] epilogue iteration ----
    for (int t = 0; t <= SEQ; t++) {
        const bf16* hsrc = g_hs + (size_t)((t + 1) & 1) * HB;   // h0[t-1]

        // fused loop: rec0 + ip1 share A
        stage_A(sA, hsrc); stage_U(sU, Urow1);
        asm volatile("cp.async.commit_group;");

        float ar[2][4], ai[2][4];
#pragma unroll
        for (int f = 0; f < 2; f++)
#pragma unroll
            for (int j = 0; j < 4; j++) { ar[f][j] = 0.f; ai[f][j] = 0.f; }

#pragma unroll 1
        for (int kb = 0; kb < 16; kb++) {
            asm volatile("cp.async.wait_group 0;");
            __syncthreads();
            if (kb < 15) {
                stage_A(sA + (uint32_t)((kb + 1) & 1) * 16384u, hsrc + (kb + 1) * 64);
                stage_U(sU + (uint32_t)((kb + 1) & 1) * 8192u,  Urow1 + (kb + 1) * 64);
                asm volatile("cp.async.commit_group;");
            }
            const uint32_t ahB = sA + (uint32_t)(kb & 1) * 16384u, alB = ahB + 8192u;
            const uint32_t vhB = sV + (uint32_t)kb * 4096u, vlB = sV + (uint32_t)(16 + kb) * 4096u;
            const uint32_t uhB = sU + (uint32_t)(kb & 1) * 8192u, ulB = uhB + 4096u;
#pragma unroll
            for (int kst = 0; kst < 4; kst++) {
                const int k0 = kst * 16;
                uint32_t ah[4], al[4], bh[4], bl[4];
                ldsm4(ah, a_addr(ahB, lane, mi * 16, k0));
                ldsm4(al, a_addr(alB, lane, mi * 16, k0));
                // rec0 vs V0
                ldsm4(bh, b_addr(vhB, lane, ni * 16, k0));
                ldsm4(bl, b_addr(vlB, lane, ni * 16, k0));
                mma16816(ar[0], ah, bh[0], bh[1]);
                mma16816(ar[1], ah, bh[2], bh[3]);
                mma16816(ar[0], al, bh[0], bh[1]);
                mma16816(ar[1], al, bh[2], bh[3]);
                mma16816(ar[0], ah, bl[0], bl[1]);
                mma16816(ar[1], ah, bl[2], bl[3]);
                // ip1 vs U1
                ldsm4(bh, b_addr(uhB, lane, ni * 16, k0));
                ldsm4(bl, b_addr(ulB, lane, ni * 16, k0));
                mma16816(ai[0], ah, bh[0], bh[1]);
                mma16816(ai[1], ah, bh[2], bh[3]);
                mma16816(ai[0], al, bh[0], bh[1]);
                mma16816(ai[1], al, bh[2], bh[3]);
                mma16816(ai[0], ah, bl[0], bl[1]);
                mma16816(ai[1], ah, bl[2], bl[3]);
            }
        }

        // ip1[t-1] -> g_pre
        if (t > 0) {
            const int row = mi * 16 + epi_r;
#pragma unroll
            for (int f = 0; f < 2; f++) {
                const int col = col0 - 4 * ul + (bx * 32 ? 0 : 0) + ni * 16 + f * 8 + epi_c; // placeholder
            }
        }
        if (t > 0) {
            const int row = mi * 16 + epi_r;
#pragma unroll
            for (int f = 0; f < 2; f++) {
                const int col = bx * 32 + ni * 16 + f * 8 + epi_c;
                float* d0 = pre_out + ((size_t)(t - 1) * BATCH + row) * NG + col;
                float* d1 = pre_out + ((size_t)(t - 1) * BATCH + row + 8) * NG + col;
                __stcg(reinterpret_cast<float2*>(d0), make_float2(ai[f][0], ai[f][1]));
                __stcg(reinterpret_cast<float2*>(d1), make_float2(ai[f][2], ai[f][3]));
            }
        }
        if (t == SEQ) break;

        // rec gates -> sG
        {
            const int row = mi * 16 + epi_r;
#pragma unroll
            for (int f = 0; f < 2; f++) {
                const int col = ni * 16 + f * 8 + epi_c;
                asm volatile("st.shared.v2.f32 [%0], {%1,%2};"
                    :: "r"(sG + (uint32_t)(row * GP + col) * 4u), "f"(ar[f][0]), "f"(ar[f][1]));
                asm volatile("st.shared.v2.f32 [%0], {%1,%2};"
                    :: "r"(sG + (uint32_t)((row + 8) * GP + col) * 4u), "f"(ar[f][2]), "f"(ar[f][3]));
            }
        }
        __syncthreads();   // sA/sU reads done; sG stores visible

        // ip0 loop for tt = t+1 (reuses sA/sU)
        if (t + 1 < SEQ) {
            const int tt = t + 1;
            const bf16* xsrc = xs + (size_t)tt * 64 * 2048;
            stage_A(sA, xsrc); stage_U(sU, Urow0);
            asm volatile("cp.async.commit_group;");
            float a0[2][4];
#pragma unroll
            for (int f = 0; f < 2; f++)
#pragma unroll
                for (int j = 0; j < 4; j++) a0[f][j] = 0.f;
#pragma unroll 1
            for (int kb = 0; kb < 16; kb++) {
                asm volatile("cp.async.wait_group 0;");
                __syncthreads();
                if (kb < 15) {
                    stage_A(sA + (uint32_t)((kb + 1) & 1) * 16384u, xsrc + (kb + 1) * 64);
                    stage_U(sU + (uint32_t)((kb + 1) & 1) * 8192u,  Urow0 + (kb + 1) * 64);
                    asm volatile("cp.async.commit_group;");
                }
                const uint32_t ahB = sA + (uint32_t)(kb & 1) * 16384u, alB = ahB + 8192u;
                const uint32_t uhB = sU + (uint32_t)(kb & 1) * 8192u,  ulB = uhB + 4096u;
#pragma unroll
                for (int kst = 0; kst < 4; kst++) {
                    const int k0 = kst * 16;
                    uint32_t ah[4], al[4], bh[4], bl[4];
                    ldsm4(ah, a_addr(ahB, lane, mi * 16, k0));
                    ldsm4(bh, b_addr(uhB, lane, ni * 16, k0));
                    ldsm4(al, a_addr(alB, lane, mi * 16, k0));
                    ldsm4(bl, b_addr(ulB, lane, ni * 16, k0));
                    mma16816(a0[0], ah, bh[0], bh[1]);
                    mma16816(a0[1], ah, bh[2], bh[3]);
                    mma16816(a0[0], al, bh[0], bh[1]);
                    mma16816(a0[1], al, bh[2], bh[3]);
                    mma16816(a0[0], ah, bl[0], bl[1]);
                    mma16816(a0[1], ah, bl[2], bl[3]);
                }
            }
            const uint32_t pbuf = sP0 + (uint32_t)(tt & 1) * 9216u;
            const int row = mi * 16 + epi_r;
#pragma unroll
            for (int f = 0; f < 2; f++) {
                const int col = ni * 16 + f * 8 + epi_c;
                asm volatile("st.shared.v2.f32 [%0], {%1,%2};"
                    :: "r"(pbuf + (uint32_t)(row * GP + col) * 4u), "f"(a0[f][0]), "f"(a0[f][1]));
                asm volatile("st.shared.v2.f32 [%0], {%1,%2};"
                    :: "r"(pbuf + (uint32_t)((row + 8) * GP + col) * 4u), "f"(a0[f][2]), "f"(a0[f][3]));
            }
        }
        __syncthreads();

        // pointwise
        const uint32_t pcur = sP0 + (uint32_t)(t & 1) * 9216u;
        float4 ga, gb, pa, pb2;
        asm volatile("ld.shared.v4.f32 {%0,%1,%2,%3}, [%4];"
            : "=f"(ga.x), "=f"(ga.y), "=f"(ga.z), "=f"(ga.w)
            : "r"(sG + (uint32_t)(b * GP + 4 * ul) * 4u));
        asm volatile("ld.shared.v4.f32 {%0,%1,%2,%3}, [%4];"
            : "=f"(gb.x), "=f"(gb.y), "=f"(gb.z), "=f"(gb.w)
            : "r"(sG + (uint32_t)(b * GP + 4 * ul + 4) * 4u));
        asm volatile("ld.shared.v4.f32 {%0,%1,%2,%3}, [%4];"
            : "=f"(pa.x), "=f"(pa.y), "=f"(pa.z), "=f"(pa.w)
            : "r"(pcur + (uint32_t)(b * GP + 4 * ul) * 4u));
        asm volatile("ld.shared.v4.f32 {%0,%1,%2,%3}, [%4];"
            : "=f"(pb2.x), "=f"(pb2.y), "=f"(pb2.z), "=f"(pb2.w)
            : "r"(pcur + (uint32_t)(b * GP + 4 * ul + 4) * 4u));
        {
            float iv = sigmoid_acc(ga.x + pa.x + bias[0]);
            float fv = sigmoid_acc(ga.y + pa.y + bias[1]);
            float gv = tanh_acc   (ga.z + pa.z + bias[2]);
            float ov = sigmoid_acc(ga.w + pa.w + bias[3]);
            c2.x = fv * c2.x + iv * gv;
            h2.x = ov * tanh_acc(c2.x);
        }
        {
            float iv = sigmoid_acc(gb.x + pb2.x + bias[4]);
            float fv = sigmoid_acc(gb.y + pb2.y + bias[5]);
            float gv = tanh_acc   (gb.z + pb2.z + bias[6]);
            float ov = sigmoid_acc(gb.w + pb2.w + bias[7]);
            c2.y = fv * c2.y + iv * gv;
            h2.y = ov * tanh_acc(c2.y);
        }
        bf16 xh, xl, yh, yl;
        split2(h2.x, xh, xl);
        split2(h2.y, yh, yl);
        __nv_bfloat162 vhi = __halves2bfloat162(xh, yh);
        __nv_bfloat162 vlo = __halves2bfloat162(xl, yl);
        bf16* wdst = g_hs + (size_t)(t & 1) * HB + b * 2048;
        __stcg(reinterpret_cast<unsigned*>(wdst + u0g), *reinterpret_cast<unsigned*>(&vhi));
        __stcg(reinterpret_cast<unsigned*>(wdst + 1024 + u0g), *reinterpret_cast<unsigned*>(&vlo));
        grid_barrier(mygen);
    }

    *reinterpret_cast<float2*>(dh + b * HS + u0g) = h2;
    *reinterpret_cast<float2*>(dc + b * HS + u0g) = c2;
}

// =================================================================================
// PHASE 2: pure recurrent layer (R6/R7 k_layer_t, xsplit removed).
// =================================================================================
__global__ __launch_bounds__(256) void k_layer_t(
    const bf16* __restrict__ Vs, const float* __restrict__ pre,
    const float* __restrict__ b1, const float* __restrict__ b2,
    float* __restrict__ outbuf, float* __restrict__ dh, float* __restrict__ dc)
{
    extern __shared__ char dsm[];
    const uint32_t sbase = (smem_u32(dsm) + 1023u) & ~1023u;
    const uint32_t sV = sbase;
    const uint32_t sA = sbase + 131072;
    const uint32_t sG = sbase + 131072 + 32768;
    const int tid = threadIdx.x, wid = tid >> 5, lane = tid & 31;
    const int bx = blockIdx.x;
    const int mi = wid & 3, ni = wid >> 2;
    const int b  = tid >> 2;
    const int ul = (tid & 3) * 2;
    const int u0g = bx * UNITS + ul;
    const int col0 = bx * 32 + 4 * ul;

    for (int s = 0; s < 2; s++)
        for (int kb = 0; kb < 16; kb++)
            load_tile(sV + (uint32_t)(s * 16 + kb) * 4096u,
                      Vs + (size_t)(bx * 32) * 2048 + s * 1024 + kb * 64,
                      32, 2048);

    float bias[8];
#pragma unroll
    for (int j = 0; j < 8; j++) {
        int n = col0 + j;
        int orig = ((n & 3) << 10) + (n >> 2);
        bias[j] = __ldg(b1 + orig) + __ldg(b2 + orig);
    }

    unsigned mygen;
    asm volatile("ld.relaxed.gpu.u32 %0, [%1];" : "=r"(mygen) : "l"(&g_gen));

    float2 c2 = make_float2(0.f, 0.f), h2 = make_float2(0.f, 0.f);
    __stcg(reinterpret_cast<unsigned*>(g_hs + (size_t)HB + b * 2048 + u0g), 0u);
    __stcg(reinterpret_cast<unsigned*>(g_hs + (size_t)HB + b * 2048 + 1024 + u0g), 0u);
    grid_barrier(mygen);

    for (int t = 0; t < SEQ; t++) {
        const bf16* hsrc = g_hs + (size_t)((t + 1) & 1) * HB;

        const float* prow = pre + ((size_t)t * BATCH + b) * NG + col0;
        float4 p0 = __ldg(reinterpret_cast<const float4*>(prow));
        float4 p1 = __ldg(reinterpret_cast<const float4*>(prow + 4));

        stage_A(sA, hsrc);
        asm volatile("cp.async.commit_group;");

        float acc[2][4];
#pragma unroll
        for (int f = 0; f < 2; f++)
#pragma unroll
            for (int j = 0; j < 4; j++) acc[f][j] = 0.f;

#pragma unroll 1
        for (int kb = 0; kb < 16; kb++) {
            asm volatile("cp.async.wait_group 0;");
            __syncthreads();
            if (kb < 15) {
                stage_A(sA + (uint32_t)((kb + 1) & 1) * 16384u, hsrc + (kb + 1) * 64);
                asm volatile("cp.async.commit_group;");
            }
            const uint32_t ahB = sA + (uint32_t)(kb & 1) * 16384u;
            const uint32_t alB = ahB + 8192u;
            const uint32_t vhB = sV + (uint32_t)kb * 4096u;
            const uint32_t vlB = sV + (uint32_t)(16 + kb) * 4096u;
#pragma unroll
            for (int kst = 0; kst < 4; kst++) {
                const int k0 = kst * 16;
                uint32_t ah[4], al[4], bh[4], bl[4];
                ldsm4(ah, a_addr(ahB, lane, mi * 16, k0));
                ldsm4(bh, b_addr(vhB, lane, ni * 16, k0));
                ldsm4(al, a_addr(alB, lane, mi * 16, k0));
                ldsm4(bl, b_addr(vlB, lane, ni * 16, k0));
                mma16816(acc[0], ah, bh[0], bh[1]);
                mma16816(acc[1], ah, bh[2], bh[3]);
                mma16816(acc[0], al, bh[0], bh[1]);
                mma16816(acc[1], al, bh[2], bh[3]);
                mma16816(acc[0], ah, bl[0], bl[1]);
                mma16816(acc[1], ah, bl[2], bl[3]);
            }
        }

        {
            const int r = lane >> 2, cq = (lane & 3) * 2;
            const int row = mi * 16 + r;
#pragma unroll
            for (int f = 0; f < 2; f++) {
                const int col = ni * 16 + f * 8 + cq;
                asm volatile("st.shared.v2.f32 [%0], {%1,%2};"
                    :: "r"(sG + (uint32_t)(row * GP + col) * 4u), "f"(acc[f][0]), "f"(acc[f][1]));
                asm volatile("st.shared.v2.f32 [%0], {%1,%2};"
                    :: "r"(sG + (uint32_t)((row + 8) * GP + col) * 4u), "f"(acc[f][2]), "f"(acc[f][3]));
            }
        }
        __syncthreads();

        float4 ga, gb;
        asm volatile("ld.shared.v4.f32 {%0,%1,%2,%3}, [%4];"
            : "=f"(ga.x), "=f"(ga.y), "=f"(ga.z), "=f"(ga.w)
            : "r"(sG + (uint32_t)(b * GP + 4 * ul) * 4u));
        asm volatile("ld.shared.v4.f32 {%0,%1,%2,%3}, [%4];"
            : "=f"(gb.x), "=f"(gb.y), "=f"(gb.z), "=f"(gb.w)
            : "r"(sG + (uint32_t)(b * GP + 4 * ul + 4) * 4u));
        {
            float iv = sigmoid_acc(ga.x + p0.x + bias[0]);
            float fv = sigmoid_acc(ga.y + p0.y + bias[1]);
            float gv = tanh_acc   (ga.z + p0.z + bias[2]);
            float ov = sigmoid_acc(ga.w + p0.w + bias[3]);
            c2.x = fv * c2.x + iv * gv;
            h2.x = ov * tanh_acc(c2.x);
        }
        {
            float iv = sigmoid_acc(gb.x + p1.x + bias[4]);
            float fv = sigmoid_acc(gb.y + p1.y + bias[5]);
            float gv = tanh_acc   (gb.z + p1.z + bias[6]);
            float ov = sigmoid_acc(gb.w + p1.w + bias[7]);
            c2.y = fv * c2.y + iv * gv;
            h2.y = ov * tanh_acc(c2.y);
        }

        bf16 xh, xl, yh, yl;
        split2(h2.x, xh, xl);
        split2(h2.y, yh, yl);
        __nv_bfloat162 vhi = __halves2bfloat162(xh, yh);
        __nv_bfloat162 vlo = __halves2bfloat162(xl, yl);
        bf16* wdst = g_hs + (size_t)(t & 1) * HB + b * 2048;
        __stcg(reinterpret_cast<unsigned*>(wdst + u0g), *reinterpret_cast<unsigned*>(&vhi));
        __stcg(reinterpret_cast<unsigned*>(wdst + 1024 + u0g), *reinterpret_cast<unsigned*>(&vlo));
        if (outbuf)
            *reinterpret_cast<float2*>(outbuf + ((size_t)t * BATCH + b) * HS + u0g) = h2;
        grid_barrier(mygen);
    }

    *reinterpret_cast<float2*>(dh + b * HS + u0g) = h2;
    *reinterpret_cast<float2*>(dc + b * HS + u0g) = c2;
}

// =================================================================================
extern "C" void kernel_launch(void* const* d_in, const int* in_sizes, int n_in,
                              void* d_out, int out_size)
{
    const float* x   = (const float*)d_in[0];
    const float* U0  = (const float*)d_in[1];
    const float* V0  = (const float*)d_in[2];
    const float* bi0 = (const float*)d_in[3];
    const float* bh0 = (const float*)d_in[4];
    const float* U1  = (const float*)d_in[5];
    const float* V1  = (const float*)d_in[6];
    const float* bi1 = (const float*)d_in[7];
    const float* bh1 = (const float*)d_in[8];
    float* out = (float*)d_out;

    cudaFuncSetAttribute(k_phase1,  cudaFuncAttributeMaxDynamicSharedMemorySize, SMEM_P1);
    cudaFuncSetAttribute(k_layer_t, cudaFuncAttributeMaxDynamicSharedMemorySize, SMEM_LAYER);

    float *pre = nullptr;
    bf16 *xs = nullptr, *us0 = nullptr, *vs0 = nullptr, *us1 = nullptr, *vs1 = nullptr;
    cudaGetSymbolAddress((void**)&pre, g_pre);
    cudaGetSymbolAddress((void**)&xs,  g_xs);
    cudaGetSymbolAddress((void**)&us0, g_Us0);
    cudaGetSymbolAddress((void**)&vs0, g_Vs0);
    cudaGetSymbolAddress((void**)&us1, g_Us1);
    cudaGetSymbolAddress((void**)&vs1, g_Vs1);

    const size_t O_OUT = (size_t)SEQ * BATCH * HS;
    const size_t BH    = (size_t)BATCH * HS;

    k_split_x<<<(MROWS * HS) / 256, 256>>>(x);
    {
        dim3 gsw((NG * HS) / 256, 4);
        k_split_w4<<<gsw, 256>>>(U0, V0, U1, V1, us0, vs0, us1, vs1);
    }

    // phase 1: layer-0 recurrence + both input projections fused
    k_phase1<<<NB_PERS, 256, SMEM_P1>>>(vs0, us0, us1, xs, bi0, bh0, pre,
                                        out + O_OUT,            // h_f[0]
                                        out + O_OUT + 2 * BH);  // c_f[0]

    // phase 2: layer-1 recurrence (pre from phase 1), bias = bi1+bh1
    k_layer_t<<<NB_PERS, 256, SMEM_LAYER>>>(vs1, pre, bi1, bh1, out,
                                            out + O_OUT + BH,       // h_f[1]
                                            out + O_OUT + 3 * BH);  // c_f[1]
}

// round 9
// speedup vs baseline: 1.1622x; 1.1622x over previous
#include <cuda_runtime.h>
#include <cuda_bf16.h>
#include <cstdint>
#include <cstddef>

#define SEQ   512
#define BATCH 64
#define HS    1024
#define NG    4096
#define MROWS (SEQ*BATCH)     // 32768
#define NB_PERS 128
#define UNITS 8               // hidden units per CTA
#define GP 36                 // padded gate-smem row stride (floats)
#define HB (BATCH*2*HS)       // one h buffer (hi|lo), elements
#define SMEM_LAYER (1024 + 131072 + 32768 + 9216 + 256)
#define NCHUNK 32             // inproj k-chunks of 32
#define NSTAGE 4
#define SMEM_INPROJ (NSTAGE*32768 + 1024)

typedef unsigned long long u64;
typedef __nv_bfloat16 bf16;

// ---------------- static device scratch ----------------
__device__ float g_pre[(size_t)MROWS * NG];          // gate pre-activations (permuted cols)
__device__ bf16  g_xs[(size_t)MROWS * 2 * HS];       // input splits (hi|lo); layer0 h splits
__device__ bf16  g_hs[2 * HB];                       // double-buffered h splits
__device__ bf16  g_Us0[(size_t)NG * 2 * HS];         // permuted weight splits
__device__ bf16  g_Vs0[(size_t)NG * 2 * HS];
__device__ bf16  g_Us1[(size_t)NG * 2 * HS];
__device__ bf16  g_Vs1[(size_t)NG * 2 * HS];

// ---------------- grid barrier (release/acquire, monotonic gen) ----------------
__device__ unsigned g_cnt = 0;
__device__ unsigned g_gen = 0;

__device__ __forceinline__ void grid_barrier(unsigned& mygen) {
    __syncthreads();
    if (threadIdx.x == 0) {
        unsigned old;
        asm volatile("atom.add.acq_rel.gpu.u32 %0, [%1], 1;"
                     : "=r"(old) : "l"(&g_cnt) : "memory");
        if (old == (unsigned)(NB_PERS - 1)) {
            asm volatile("st.relaxed.gpu.u32 [%0], 0;" :: "l"(&g_cnt) : "memory");
            asm volatile("red.release.gpu.add.u32 [%0], 1;" :: "l"(&g_gen) : "memory");
        } else {
            unsigned cur;
            do {
                __nanosleep(20);
                asm volatile("ld.acquire.gpu.u32 %0, [%1];"
                             : "=r"(cur) : "l"(&g_gen) : "memory");
            } while (cur == mygen);
        }
    }
    mygen += 1;
    __syncthreads();
}

// ---------------- mma.sync building blocks (validated R4-R8) ----------------
__device__ __forceinline__ uint32_t smem_u32(const void* p) {
    uint32_t a;
    asm("{ .reg .u64 t; cvta.to.shared.u64 t, %1; cvt.u32.u64 %0, t; }" : "=r"(a) : "l"(p));
    return a;
}
__device__ __forceinline__ void ldsm4(uint32_t* f, uint32_t addr) {
    asm volatile("ldmatrix.sync.aligned.m8n8.x4.shared.b16 {%0,%1,%2,%3}, [%4];"
        : "=r"(f[0]), "=r"(f[1]), "=r"(f[2]), "=r"(f[3]) : "r"(addr));
}
__device__ __forceinline__ void mma16816(float* d, const uint32_t* a, uint32_t b0, uint32_t b1) {
    asm volatile("mma.sync.aligned.m16n8k16.row.col.f32.bf16.bf16.f32 "
        "{%0,%1,%2,%3}, {%4,%5,%6,%7}, {%8,%9}, {%0,%1,%2,%3};"
        : "+f"(d[0]), "+f"(d[1]), "+f"(d[2]), "+f"(d[3])
        : "r"(a[0]), "r"(a[1]), "r"(a[2]), "r"(a[3]), "r"(b0), "r"(b1));
}
__device__ __forceinline__ uint32_t swz(uint32_t r, uint32_t c16) {
    return r * 128u + ((c16 ^ (r & 7u)) << 4);
}
__device__ __forceinline__ uint32_t a_addr(uint32_t base, int lane, int m0, int k0) {
    int sel = lane >> 3;
    uint32_t row = (uint32_t)(m0 + (lane & 7) + ((sel & 1) << 3));
    uint32_t c16 = (uint32_t)((k0 >> 3) + (sel >> 1));
    return base + swz(row, c16);
}
__device__ __forceinline__ uint32_t b_addr(uint32_t base, int lane, int n0, int k0) {
    int sel = lane >> 3;
    uint32_t row = (uint32_t)(n0 + (lane & 7) + ((sel >> 1) << 3));
    uint32_t c16 = (uint32_t)((k0 >> 3) + (sel & 1));
    return base + swz(row, c16);
}
__device__ __forceinline__ void cp16(uint32_t dst, const void* src) {
    asm volatile("cp.async.cg.shared.global [%0], [%1], 16;" :: "r"(dst), "l"(src));
}

// load a [rows x 64] bf16 tile (row stride ld elems) into swizzled smem (sync path)
__device__ __forceinline__ void load_tile(uint32_t sdst, const bf16* __restrict__ src,
                                          int rows, int ld) {
    const int chunks = rows * 8;
    for (int i = threadIdx.x; i < chunks; i += 256) {
        int r = i >> 3, c = i & 7;
        const uint4* p = reinterpret_cast<const uint4*>(src + (size_t)r * ld + c * 8);
        uint4 v = __ldg(p);
        asm volatile("st.shared.v4.b32 [%0], {%1,%2,%3,%4};"
                     :: "r"(sdst + swz((uint32_t)r, (uint32_t)c)),
                        "r"(v.x), "r"(v.y), "r"(v.z), "r"(v.w));
    }
}
// async stage of a combined [128 x 64] tile: cols 0-31 = hi k-chunk, 32-63 = lo.
// src points at the hi row base (k offset applied); lo is +1024 elems.
__device__ __forceinline__ void stage_tile_hilo(uint32_t sdst, const bf16* __restrict__ src) {
    const int tid = threadIdx.x;
#pragma unroll
    for (int q = 0; q < 4; q++) {
        int i = tid + q * 256;               // 0..1023
        int r = i >> 3, c = i & 7;
        const bf16* s = src + (size_t)r * 2048 + (c < 4 ? c * 8 : 1024 + (c - 4) * 8);
        cp16(sdst + swz((uint32_t)r, (uint32_t)c), s);
    }
}
// async stage: A pair (64 rows x 64 cols, hi tile + lo tile of 8KB each)
__device__ __forceinline__ void stage_A(uint32_t sdst, const bf16* __restrict__ src) {
    const int tid = threadIdx.x;
#pragma unroll
    for (int s = 0; s < 2; s++) {
#pragma unroll
        for (int q = 0; q < 2; q++) {
            int i = tid + q * 256;
            int r = i >> 3, c = i & 7;
            cp16(sdst + (uint32_t)s * 8192u + swz((uint32_t)r, (uint32_t)c),
                 src + s * 1024 + (size_t)r * 2048 + c * 8);
        }
    }
}

// ---------------- activations ----------------
__device__ __forceinline__ float sigmoid_acc(float x) {
    return 1.0f / (1.0f + __expf(-x));
}
__device__ __forceinline__ float tanh_acc(float x) {
    float e = __expf(-2.0f * fabsf(x));
    float t = (1.0f - e) / (1.0f + e);
    return copysignf(t, x);
}
__device__ __forceinline__ void split2(float v, bf16& hi, bf16& lo) {
    hi = __float2bfloat16(v);
    lo = __float2bfloat16(v - __bfloat162float(hi));
}

// =================================================================================
// split kernels. Weight rows gate-permuted: orig row r = g*1024+u -> 4u+g.
// =================================================================================
__global__ __launch_bounds__(256) void k_split_x(const float* __restrict__ x) {
    size_t i = (size_t)blockIdx.x * 256 + threadIdx.x;
    size_t m = i >> 10, k = i & 1023;
    bf16 hi, lo; split2(x[i], hi, lo);
    g_xs[m * 2048 + k]        = hi;
    g_xs[m * 2048 + 1024 + k] = lo;
}
__global__ __launch_bounds__(256) void k_split_w4(
    const float* __restrict__ W0, const float* __restrict__ W1,
    const float* __restrict__ W2, const float* __restrict__ W3,
    bf16* __restrict__ d0, bf16* __restrict__ d1,
    bf16* __restrict__ d2, bf16* __restrict__ d3)
{
    const float* W; bf16* dst;
    switch (blockIdx.y) {
        case 0:  W = W0; dst = d0; break;
        case 1:  W = W1; dst = d1; break;
        case 2:  W = W2; dst = d2; break;
        default: W = W3; dst = d3; break;
    }
    size_t i = (size_t)blockIdx.x * 256 + threadIdx.x;
    size_t n = i >> 10, k = i & 1023;
    size_t gidx = n >> 10, u = n & 1023;
    size_t np = u * 4 + gidx;
    bf16 hi, lo; split2(W[i], hi, lo);
    dst[np * 2048 + k]        = hi;
    dst[np * 2048 + 1024 + k] = lo;
}

// =================================================================================
// Input projection, 4-stage cp.async pipeline, 1 CTA/SM, FULL register budget
// (launch_bounds(256) — the (256,2) cap at 128 regs was spilling the 64 fp32
// accumulators to local memory; that was the 35%-of-ceiling bug).
// Stage = {A_hilo 128x64, B_hilo 128x64} = 32KB; K-chunk 32; 32 chunks.
// =================================================================================
__global__ __launch_bounds__(256) void k_inproj_t(
    const bf16* __restrict__ A, const bf16* __restrict__ W,
    float* __restrict__ C)
{
    extern __shared__ char dsm[];
    const uint32_t sbase = (smem_u32(dsm) + 1023u) & ~1023u;
    const int tid = threadIdx.x, wid = tid >> 5, lane = tid & 31;
    const int m0 = blockIdx.y * 128, n0 = blockIdx.x * 128;
    const int mi = wid & 3, ni = wid >> 2;

    const bf16* Arow = A + (size_t)m0 * 2048;
    const bf16* Wrow = W + (size_t)n0 * 2048;

    auto issue_stage = [&](int kb) {
        const uint32_t st = sbase + (uint32_t)(kb % NSTAGE) * 32768u;
        stage_tile_hilo(st,          Arow + kb * 32);
        stage_tile_hilo(st + 16384u, Wrow + kb * 32);
        asm volatile("cp.async.commit_group;");
    };

    float acc[2][8][4];
#pragma unroll
    for (int a = 0; a < 2; a++)
#pragma unroll
        for (int b = 0; b < 8; b++)
#pragma unroll
            for (int cpos = 0; cpos < 4; cpos++) acc[a][b][cpos] = 0.f;

    issue_stage(0);
    issue_stage(1);
    issue_stage(2);

#pragma unroll 1
    for (int kb = 0; kb < NCHUNK; kb++) {
        if (kb >= NCHUNK - 1)      asm volatile("cp.async.wait_group 0;");
        else if (kb == NCHUNK - 2) asm volatile("cp.async.wait_group 1;");
        else                       asm volatile("cp.async.wait_group 2;");
        __syncthreads();
        if (kb + 3 < NCHUNK) issue_stage(kb + 3);

        const uint32_t st = sbase + (uint32_t)(kb % NSTAGE) * 32768u;
        const uint32_t sA = st, sB = st + 16384u;
#pragma unroll
        for (int ks = 0; ks < 2; ks++) {
            const int k0 = ks * 16;
            uint32_t ah[2][4], al[2][4];
#pragma unroll
            for (int mf = 0; mf < 2; mf++) {
                ldsm4(ah[mf], a_addr(sA, lane, mi * 32 + mf * 16, k0));
                ldsm4(al[mf], a_addr(sA, lane, mi * 32 + mf * 16, k0 + 32));
            }
#pragma unroll
            for (int np = 0; np < 4; np++) {
                const int nt = ni * 64 + np * 16;
                uint32_t bh[4], bl[4];
                ldsm4(bh, b_addr(sB, lane, nt, k0));
#pragma unroll
                for (int mf = 0; mf < 2; mf++) {
                    mma16816(acc[mf][np * 2],     ah[mf], bh[0], bh[1]);
                    mma16816(acc[mf][np * 2 + 1], ah[mf], bh[2], bh[3]);
                    mma16816(acc[mf][np * 2],     al[mf], bh[0], bh[1]);
                    mma16816(acc[mf][np * 2 + 1], al[mf], bh[2], bh[3]);
                }
                ldsm4(bl, b_addr(sB, lane, nt, k0 + 32));
#pragma unroll
                for (int mf = 0; mf < 2; mf++) {
                    mma16816(acc[mf][np * 2],     ah[mf], bl[0], bl[1]);
                    mma16816(acc[mf][np * 2 + 1], ah[mf], bl[2], bl[3]);
                }
            }
        }
    }

    const int r = lane >> 2, cq = (lane & 3) * 2;
#pragma unroll
    for (int mf = 0; mf < 2; mf++) {
#pragma unroll
        for (int nf = 0; nf < 8; nf++) {
            const int ncol = n0 + ni * 64 + nf * 8 + cq;
            const int row0 = m0 + mi * 32 + mf * 16 + r;
            *reinterpret_cast<float2*>(C + (size_t)row0 * NG + ncol) =
                make_float2(acc[mf][nf][0], acc[mf][nf][1]);
            *reinterpret_cast<float2*>(C + (size_t)(row0 + 8) * NG + ncol) =
                make_float2(acc[mf][nf][2], acc[mf][nf][3]);
        }
    }
}

// =================================================================================
// Persistent LSTM layer (R6/R7 k_layer_t — known good, at mma ceiling in window).
// =================================================================================
__global__ __launch_bounds__(256) void k_layer_t(
    const bf16* __restrict__ Vs, const float* __restrict__ pre,
    const float* __restrict__ b1, const float* __restrict__ b2,
    float* __restrict__ outbuf, bf16* __restrict__ xsplit,
    float* __restrict__ dh, float* __restrict__ dc)
{
    extern __shared__ char dsm[];
    const uint32_t sbase = (smem_u32(dsm) + 1023u) & ~1023u;
    const uint32_t sV = sbase;
    const uint32_t sA = sbase + 131072;
    const uint32_t sG = sbase + 131072 + 32768;
    const int tid = threadIdx.x, wid = tid >> 5, lane = tid & 31;
    const int bx = blockIdx.x;
    const int mi = wid & 3, ni = wid >> 2;
    const int b  = tid >> 2;
    const int ul = (tid & 3) * 2;
    const int u0g = bx * UNITS + ul;
    const int col0 = bx * 32 + 4 * ul;

    for (int s = 0; s < 2; s++)
        for (int kb = 0; kb < 16; kb++)
            load_tile(sV + (uint32_t)(s * 16 + kb) * 4096u,
                      Vs + (size_t)(bx * 32) * 2048 + s * 1024 + kb * 64,
                      32, 2048);

    float bias[8];
#pragma unroll
    for (int j = 0; j < 8; j++) {
        int n = col0 + j;
        int orig = ((n & 3) << 10) + (n >> 2);
        bias[j] = __ldg(b1 + orig) + __ldg(b2 + orig);
    }

    unsigned mygen;
    asm volatile("ld.relaxed.gpu.u32 %0, [%1];" : "=r"(mygen) : "l"(&g_gen));

    float2 c2 = make_float2(0.f, 0.f), h2 = make_float2(0.f, 0.f);
    __stcg(reinterpret_cast<unsigned*>(g_hs + (size_t)HB + b * 2048 + u0g), 0u);
    __stcg(reinterpret_cast<unsigned*>(g_hs + (size_t)HB + b * 2048 + 1024 + u0g), 0u);
    grid_barrier(mygen);

    for (int t = 0; t < SEQ; t++) {
        const bf16* hsrc = g_hs + (size_t)((t + 1) & 1) * HB;

        const float* prow = pre + ((size_t)t * BATCH + b) * NG + col0;
        float4 p0 = __ldg(reinterpret_cast<const float4*>(prow));
        float4 p1 = __ldg(reinterpret_cast<const float4*>(prow + 4));

        stage_A(sA, hsrc);
        asm volatile("cp.async.commit_group;");

        float acc[2][4];
#pragma unroll
        for (int f = 0; f < 2; f++)
#pragma unroll
            for (int j = 0; j < 4; j++) acc[f][j] = 0.f;

#pragma unroll 1
        for (int kb = 0; kb < 16; kb++) {
            asm volatile("cp.async.wait_group 0;");
            __syncthreads();
            if (kb < 15) {
                stage_A(sA + (uint32_t)((kb + 1) & 1) * 16384u, hsrc + (kb + 1) * 64);
                asm volatile("cp.async.commit_group;");
            }
            const uint32_t ahB = sA + (uint32_t)(kb & 1) * 16384u;
            const uint32_t alB = ahB + 8192u;
            const uint32_t vhB = sV + (uint32_t)kb * 4096u;
            const uint32_t vlB = sV + (uint32_t)(16 + kb) * 4096u;
#pragma unroll
            for (int kst = 0; kst < 4; kst++) {
                const int k0 = kst * 16;
                uint32_t ah[4], al[4], bh[4], bl[4];
                ldsm4(ah, a_addr(ahB, lane, mi * 16, k0));
                ldsm4(bh, b_addr(vhB, lane, ni * 16, k0));
                ldsm4(al, a_addr(alB, lane, mi * 16, k0));
                ldsm4(bl, b_addr(vlB, lane, ni * 16, k0));
                mma16816(acc[0], ah, bh[0], bh[1]);
                mma16816(acc[1], ah, bh[2], bh[3]);
                mma16816(acc[0], al, bh[0], bh[1]);
                mma16816(acc[1], al, bh[2], bh[3]);
                mma16816(acc[0], ah, bl[0], bl[1]);
                mma16816(acc[1], ah, bl[2], bl[3]);
            }
        }

        {
            const int r = lane >> 2, cq = (lane & 3) * 2;
            const int row = mi * 16 + r;
#pragma unroll
            for (int f = 0; f < 2; f++) {
                const int col = ni * 16 + f * 8 + cq;
                asm volatile("st.shared.v2.f32 [%0], {%1,%2};"
                    :: "r"(sG + (uint32_t)(row * GP + col) * 4u), "f"(acc[f][0]), "f"(acc[f][1]));
                asm volatile("st.shared.v2.f32 [%0], {%1,%2};"
                    :: "r"(sG + (uint32_t)((row + 8) * GP + col) * 4u), "f"(acc[f][2]), "f"(acc[f][3]));
            }
        }
        __syncthreads();

        float4 ga, gb;
        asm volatile("ld.shared.v4.f32 {%0,%1,%2,%3}, [%4];"
            : "=f"(ga.x), "=f"(ga.y), "=f"(ga.z), "=f"(ga.w)
            : "r"(sG + (uint32_t)(b * GP + 4 * ul) * 4u));
        asm volatile("ld.shared.v4.f32 {%0,%1,%2,%3}, [%4];"
            : "=f"(gb.x), "=f"(gb.y), "=f"(gb.z), "=f"(gb.w)
            : "r"(sG + (uint32_t)(b * GP + 4 * ul + 4) * 4u));
        {
            float iv = sigmoid_acc(ga.x + p0.x + bias[0]);
            float fv = sigmoid_acc(ga.y + p0.y + bias[1]);
            float gv = tanh_acc   (ga.z + p0.z + bias[2]);
            float ov = sigmoid_acc(ga.w + p0.w + bias[3]);
            c2.x = fv * c2.x + iv * gv;
            h2.x = ov * tanh_acc(c2.x);
        }
        {
            float iv = sigmoid_acc(gb.x + p1.x + bias[4]);
            float fv = sigmoid_acc(gb.y + p1.y + bias[5]);
            float gv = tanh_acc   (gb.z + p1.z + bias[6]);
            float ov = sigmoid_acc(gb.w + p1.w + bias[7]);
            c2.y = fv * c2.y + iv * gv;
            h2.y = ov * tanh_acc(c2.y);
        }

        bf16 xh, xl, yh, yl;
        split2(h2.x, xh, xl);
        split2(h2.y, yh, yl);
        __nv_bfloat162 vhi = __halves2bfloat162(xh, yh);
        __nv_bfloat162 vlo = __halves2bfloat162(xl, yl);
        unsigned uhi = *reinterpret_cast<unsigned*>(&vhi);
        unsigned ulo = *reinterpret_cast<unsigned*>(&vlo);
        bf16* wdst = g_hs + (size_t)(t & 1) * HB + b * 2048;
        __stcg(reinterpret_cast<unsigned*>(wdst + u0g), uhi);
        __stcg(reinterpret_cast<unsigned*>(wdst + 1024 + u0g), ulo);
        if (outbuf)
            *reinterpret_cast<float2*>(outbuf + ((size_t)t * BATCH + b) * HS + u0g) = h2;
        if (xsplit) {
            bf16* xr = xsplit + ((size_t)t * BATCH + b) * 2048;
            *reinterpret_cast<unsigned*>(xr + u0g) = uhi;
            *reinterpret_cast<unsigned*>(xr + 1024 + u0g) = ulo;
        }
        grid_barrier(mygen);
    }

    *reinterpret_cast<float2*>(dh + b * HS + u0g) = h2;
    *reinterpret_cast<float2*>(dc + b * HS + u0g) = c2;
}

// =================================================================================
extern "C" void kernel_launch(void* const* d_in, const int* in_sizes, int n_in,
                              void* d_out, int out_size)
{
    const float* x   = (const float*)d_in[0];
    const float* U0  = (const float*)d_in[1];
    const float* V0  = (const float*)d_in[2];
    const float* bi0 = (const float*)d_in[3];
    const float* bh0 = (const float*)d_in[4];
    const float* U1  = (const float*)d_in[5];
    const float* V1  = (const float*)d_in[6];
    const float* bi1 = (const float*)d_in[7];
    const float* bh1 = (const float*)d_in[8];
    float* out = (float*)d_out;

    cudaFuncSetAttribute(k_inproj_t, cudaFuncAttributeMaxDynamicSharedMemorySize, SMEM_INPROJ);
    cudaFuncSetAttribute(k_layer_t,  cudaFuncAttributeMaxDynamicSharedMemorySize, SMEM_LAYER);

    float *pre = nullptr;
    bf16 *xs = nullptr, *us0 = nullptr, *vs0 = nullptr, *us1 = nullptr, *vs1 = nullptr;
    cudaGetSymbolAddress((void**)&pre, g_pre);
    cudaGetSymbolAddress((void**)&xs,  g_xs);
    cudaGetSymbolAddress((void**)&us0, g_Us0);
    cudaGetSymbolAddress((void**)&vs0, g_Vs0);
    cudaGetSymbolAddress((void**)&us1, g_Us1);
    cudaGetSymbolAddress((void**)&vs1, g_Vs1);

    const size_t O_OUT = (size_t)SEQ * BATCH * HS;
    const size_t BH    = (size_t)BATCH * HS;

    k_split_x<<<(MROWS * HS) / 256, 256>>>(x);
    {
        dim3 gsw((NG * HS) / 256, 4);
        k_split_w4<<<gsw, 256>>>(U0, V0, U1, V1, us0, vs0, us1, vs1);
    }

    const dim3 gIn(NG / 128, MROWS / 128);   // (32, 256)

    // layer 0 (h splits feed layer-1 inproj via g_xs)
    k_inproj_t<<<gIn, 256, SMEM_INPROJ>>>(xs, us0, pre);
    k_layer_t<<<NB_PERS, 256, SMEM_LAYER>>>(vs0, pre, bi0, bh0, nullptr, xs,
                                            out + O_OUT,            // h_f[0]
                                            out + O_OUT + 2 * BH);  // c_f[0]

    // layer 1
    k_inproj_t<<<gIn, 256, SMEM_INPROJ>>>(xs, us1, pre);
    k_layer_t<<<NB_PERS, 256, SMEM_LAYER>>>(vs1, pre, bi1, bh1, out, nullptr,
                                            out + O_OUT + BH,       // h_f[1]
                                            out + O_OUT + 3 * BH);  // c_f[1]
}